// round 9
// baseline (speedup 1.0000x reference)
#include <cuda_runtime.h>

static constexpr int NB   = 8;    // batch
static constexpr int NN   = 96;   // nodes
static constexpr int ND   = 16;   // feature dim
static constexpr int H0   = 50;
static constexpr int H1   = 50;
static constexpr int NOUT = 64;
#define NEG_SLOPE 0.05f

// Scratch (device globals: no allocation allowed in kernel_launch)
__device__ float g_dis   [NB*NN*NN];   // dis[b,i,j]
__device__ float g_sdikT [NB*NN*NN];   // sdikT[b,j,i] = sum_k adj[b,j,k]*dis[b,k,i]
__device__ float g_A     [NB*NN*H0];   // x @ W1[0:16]
__device__ float g_C     [NB*NN*H0];   // x @ W1[32:48]
__device__ float g_F     [NB*NN*H0];   // deg_j*(b1+Bm_j) + sd_j*w_jk
__device__ float g_E     [NB*NN*H0];   // F_j + adj_j @ C
__device__ float g_deg   [NB*NN];
__device__ float g_sd    [NB*NN];
__device__ float g_aggx  [NB*NN*ND];   // adj @ x
__device__ int   g_nbr   [NB*NN*NN];   // compacted neighbor indices per row
__device__ float g_nbrval[NB*NN*NN];   // adj value at each edge
__device__ int   g_ncnt  [NB*NN];      // neighbor count per row

__device__ __forceinline__ float leaky(float v) { return v >= 0.f ? v : NEG_SLOPE * v; }

// ---------------------------------------------------------------------------
// k1: grid (8 parts, NB), 192 threads. 12 i-rows per block, all math in shared.
// Emits: dis, deg, sd, aggx, A, C, F, and compacted nbr lists.
// ---------------------------------------------------------------------------
__global__ void k1(const float* __restrict__ x, const float* __restrict__ adj,
                   const float* __restrict__ W1, const float* __restrict__ b1) {
    const int i0 = blockIdx.x * 12, b = blockIdx.y;
    const int tid = threadIdx.x;                     // 0..191
    __shared__ float sx[NN * 17];                    // padded
    __shared__ float sW1[51 * H0];
    __shared__ float sb1[H0];
    __shared__ float sadj[12 * 97];
    __shared__ float sdisr[12 * 97];
    __shared__ float sdeg[12], ssd[12];

    // phase0: bulk loads, max MLP
    const float* xb = x + b * NN * ND;
    #pragma unroll
    for (int p = tid; p < NN * ND; p += 192) sx[(p >> 4) * 17 + (p & 15)] = xb[p];
    for (int p = tid; p < 51 * H0; p += 192) sW1[p] = W1[p];
    if (tid < H0) sb1[tid] = b1[tid];
    #pragma unroll
    for (int p = tid; p < 12 * NN; p += 192) {
        int r = p / NN, j = p - r * NN;
        sadj[r * 97 + j] = adj[(b * NN + i0 + r) * NN + j];
    }
    __syncthreads();

    // phase1: dis (6 pairs per thread)
    #pragma unroll
    for (int p = tid; p < 12 * NN; p += 192) {
        int r = p / NN, j = p - r * NN;
        int i = i0 + r;
        float acc = 1e-10f;
        #pragma unroll
        for (int d = 0; d < ND; d++) {
            float df = sx[i * 17 + d] - sx[j * 17 + d];
            acc += df * df;
        }
        float dv = sqrtf(acc);
        sdisr[r * 97 + j] = dv;
        g_dis[(b * NN + i) * NN + j] = dv;
    }
    __syncthreads();

    // phase2a: neighbor-list scan + deg/sd (threads 0..11, serial per row)
    if (tid < 12) {
        int r = tid, bi = b * NN + i0 + r;
        float deg = 0.f, sd = 0.f;
        int cnt = 0;
        for (int j = 0; j < NN; j++) {
            float a = sadj[r * 97 + j];
            if (a != 0.f) {
                g_nbr   [bi * NN + cnt] = j;
                g_nbrval[bi * NN + cnt] = a;
                cnt++;
                deg += a;
                sd  += a * sdisr[r * 97 + j];
            }
        }
        g_ncnt[bi] = cnt;
        sdeg[r] = deg;  ssd[r] = sd;
        g_deg[bi] = deg; g_sd[bi] = sd;
    }
    // phase2b: aggx (all 192 threads, exactly 12*16 outputs)
    {
        int r = tid >> 4, d = tid & 15;
        float s = 0.f;
        for (int j = 0; j < NN; j++) s += sadj[r * 97 + j] * sx[j * 17 + d];
        g_aggx[(b * NN + i0 + r) * ND + d] = s;
    }
    __syncthreads();

    // phase3: A / C / F rows (shared-only FMA)
    for (int p = tid; p < 12 * H0; p += 192) {
        int r = p / H0, h = p - r * H0;
        int bi = b * NN + i0 + r;
        float a0 = 0.f, bm = 0.f, c = 0.f;
        #pragma unroll
        for (int d = 0; d < ND; d++) {
            float xv = sx[(i0 + r) * 17 + d];
            a0 += xv * sW1[d * H0 + h];
            bm += xv * sW1[(ND + d) * H0 + h];
            c  += xv * sW1[(2 * ND + d) * H0 + h];
        }
        g_A[bi * H0 + h] = a0;
        g_C[bi * H0 + h] = c;
        g_F[bi * H0 + h] = sdeg[r] * (sb1[h] + bm) + ssd[r] * sW1[49 * H0 + h];
    }
}

// ---------------------------------------------------------------------------
// k2: grid (8 parts, NB), 192 threads. 12 j-rows per block.
// Whole dis[b] + C[b] staged in shared; nbr lists staged; pure shared math.
// ---------------------------------------------------------------------------
__global__ void k2() {
    const int j0 = blockIdx.x * 12, b = blockIdx.y;
    const int tid = threadIdx.x;                     // 0..191
    __shared__ float sdis[NN * 97];                  // [k][i], 37.2 KB
    __shared__ float sC[NN * H0];                    // 19.2 KB
    __shared__ int   snb[12 * NN];
    __shared__ float snv[12 * NN];

    const float* db = g_dis + b * NN * NN;
    for (int p = tid; p < NN * NN; p += 192) {
        int k = p / NN, i = p - k * NN;
        sdis[k * 97 + i] = db[p];
    }
    const float* Cb = g_C + b * NN * H0;
    for (int p = tid; p < NN * H0; p += 192) sC[p] = Cb[p];
    for (int p = tid; p < 12 * NN; p += 192) {
        snb[p] = g_nbr   [(b * NN + j0) * NN + p];
        snv[p] = g_nbrval[(b * NN + j0) * NN + p];
    }
    __syncthreads();

    // sdikT: warp per j (6 warps, 2 iterations), lane = base i
    {
        int warp = tid >> 5, lane = tid & 31;
        #pragma unroll
        for (int iter = 0; iter < 2; iter++) {
            int r = warp + 6 * iter;                 // 0..11
            int bj = b * NN + j0 + r;
            int n = g_ncnt[bj];
            float acc0 = 0.f, acc1 = 0.f, acc2 = 0.f;
            for (int e = 0; e < n; e++) {
                int k = snb[r * NN + e];
                float a = snv[r * NN + e];
                acc0 += a * sdis[k * 97 + lane];
                acc1 += a * sdis[k * 97 + lane + 32];
                acc2 += a * sdis[k * 97 + lane + 64];
            }
            g_sdikT[bj * NN + lane]      = acc0;
            g_sdikT[bj * NN + lane + 32] = acc1;
            g_sdikT[bj * NN + lane + 64] = acc2;
        }
    }
    // E rows
    for (int p = tid; p < 12 * H0; p += 192) {
        int r = p / H0, h = p - r * H0;
        int bj = b * NN + j0 + r;
        float acc = g_F[bj * H0 + h];
        int n = g_ncnt[bj];
        for (int e = 0; e < n; e++)
            acc += snv[r * NN + e] * sC[snb[r * NN + e] * H0 + h];
        g_E[bj * H0 + h] = acc;
    }
}

// ---------------------------------------------------------------------------
// k3: grid (48 pairs, NB), 128 threads = two 64-thread halves, one node each.
// Weights staged once per block; edge loop is shared-memory-only.
// ---------------------------------------------------------------------------
__global__ void k3(const float* __restrict__ x, const float* __restrict__ W1,
                   const float* __restrict__ W2, const float* __restrict__ b2,
                   const float* __restrict__ W3, const float* __restrict__ b3,
                   float* __restrict__ out) {
    const int b = blockIdx.y;
    const int tid = threadIdx.x;
    const int half = tid >> 6;                       // 0 or 1
    const int t = tid & 63;
    const int i = blockIdx.x * 2 + half;
    const int bi = b * NN + i;

    __shared__ float sWm[H0 * H1];                   // W2 m3 block, 10 KB
    __shared__ float sW2a[33 * H1];                  // W2 linear rows, 6.6 KB
    __shared__ float sW3[66 * NOUT];                 // 16.9 KB
    __shared__ float sE[2][32 * 52];                 // staged E rows (cap 32)
    __shared__ int   snbr[2][NN];
    __shared__ float sval[2][NN];
    __shared__ float sdisr[2][NN];
    __shared__ float sP[2][NN], sQ[2][NN], sR[2][NN];
    __shared__ float sxi[2][ND], sax[2][ND];
    __shared__ float stsum[2][52], sm2[2][52];
    __shared__ int   sn[2];

    // phase0: bulk loads
    for (int p = tid; p < H0 * H1;   p += 128) sWm[p]  = W2[33 * H1 + p];
    for (int p = tid; p < 33 * H1;   p += 128) sW2a[p] = W2[p];
    for (int p = tid; p < 66 * NOUT; p += 128) sW3[p]  = W3[p];
    for (int p = t; p < NN; p += 64) {
        snbr [half][p] = g_nbr   [bi * NN + p];
        sval [half][p] = g_nbrval[bi * NN + p];
        sdisr[half][p] = g_dis   [bi * NN + p];
    }
    if (t == 0) sn[half] = g_ncnt[bi];
    if (t < ND) { sxi[half][t] = x[bi * ND + t]; sax[half][t] = g_aggx[bi * ND + t]; }
    float rA = 0.f, rwij = 0.f, rwik = 0.f, rb2 = 0.f;
    if (t < H0) {
        rA   = g_A[bi * H0 + t];
        rwij = W1[48 * H0 + t];
        rwik = W1[50 * H0 + t];
        rb2  = b2[t];
    }
    const float rdegi = g_deg[bi];
    const float rsdi  = g_sd[bi];
    const float rb3   = b3[t];
    __syncthreads();

    const int n = sn[half];
    // phase1: per-edge scalars (one thread per edge) + E staging (MLP ~8)
    for (int e = t; e < n; e += 64) {
        int bj = b * NN + snbr[half][e];
        float dj = g_deg[bj];
        sP[half][e] = dj;
        sQ[half][e] = dj * sdisr[half][snbr[half][e]];
        sR[half][e] = g_sdikT[bj * NN + i];
    }
    {
        int nst = n < 32 ? n : 32;
        for (int p = t; p < nst * H0; p += 64) {
            int e = p / H0, h = p - e * H0;
            sE[half][e * 52 + h] = g_E[(b * NN + snbr[half][e]) * H0 + h];
        }
    }
    __syncthreads();

    // phase2: edge loop, shared-only
    if (t < H0) {
        float tsum = 0.f;
        for (int e = 0; e < n; e++) {
            float Ev = (e < 32) ? sE[half][e * 52 + t]
                                : g_E[(b * NN + snbr[half][e]) * H0 + t];
            float S = fmaf(sP[half][e], rA,
                      fmaf(sQ[half][e], rwij,
                      fmaf(sR[half][e], rwik, Ev)));
            float av = sval[half][e];
            tsum += av * leaky(av * S);
        }
        stsum[half][t] = tsum;
    }
    __syncthreads();

    // phase3: 50x50 matvec + factored linear terms -> m2_sum
    if (t < H1) {
        float acc = 0.f;
        #pragma unroll
        for (int h = 0; h < H0; h++) acc += stsum[half][h] * sWm[h * H1 + t];
        float s1 = 0.f, s2 = 0.f;
        #pragma unroll
        for (int d = 0; d < ND; d++) {
            s1 += sxi[half][d] * sW2a[d * H1 + t];
            s2 += sax[half][d] * sW2a[(ND + d) * H1 + t];
        }
        acc += rdegi * (s1 + rb2) + s2 + rsdi * sW2a[2 * ND * H1 + t];
        sm2[half][t] = leaky(acc);
    }
    __syncthreads();

    // phase4: output GEMV (64 threads per half = NOUT)
    {
        float s = rb3;
        #pragma unroll
        for (int d = 0; d < ND; d++) s += sxi[half][d] * sW3[d * NOUT + t];
        #pragma unroll 10
        for (int h = 0; h < H1; h++) s += sm2[half][h] * sW3[(ND + h) * NOUT + t];
        out[bi * NOUT + t] = leaky(s);
    }
}

extern "C" void kernel_launch(void* const* d_in, const int* in_sizes, int n_in,
                              void* d_out, int out_size) {
    const float* x   = (const float*)d_in[0];
    const float* adj = (const float*)d_in[1];
    const float* W1  = (const float*)d_in[2];
    const float* b1  = (const float*)d_in[3];
    const float* W2  = (const float*)d_in[4];
    const float* b2  = (const float*)d_in[5];
    const float* W3  = (const float*)d_in[6];
    const float* b3  = (const float*)d_in[7];
    float* out = (float*)d_out;

    k1<<<dim3(8, NB), 192>>>(x, adj, W1, b1);
    k2<<<dim3(8, NB), 192>>>();
    k3<<<dim3(48, NB), 128>>>(x, W1, W2, b2, W3, b3, out);
}

// round 10
// speedup vs baseline: 2.2432x; 2.2432x over previous
#include <cuda_runtime.h>

static constexpr int NB   = 8;    // batch
static constexpr int NN   = 96;   // nodes
static constexpr int ND   = 16;   // feature dim
static constexpr int H0   = 50;
static constexpr int H1   = 50;
static constexpr int NOUT = 64;
static constexpr int ECH  = 48;   // k3 E-staging chunk
#define NEG_SLOPE 0.05f

// Scratch (device globals: no allocation allowed in kernel_launch)
__device__ float g_dis   [NB*NN*NN];   // dis[b,i,j]
__device__ float g_sdikT [NB*NN*NN];   // sdikT[b,j,i] = sum_k adj[b,j,k]*dis[b,k,i]
__device__ float g_A     [NB*NN*H0];   // x @ W1[0:16]
__device__ float g_E     [NB*NN*H0];   // deg_j*(b1+Bm_j) + sd_j*w_jk + aggx_j@Wc
__device__ float g_deg   [NB*NN];
__device__ float g_sd    [NB*NN];
__device__ float g_aggx  [NB*NN*ND];   // adj @ x
__device__ int   g_nbr   [NB*NN*NN];   // compacted neighbor indices per row
__device__ float g_nbrval[NB*NN*NN];   // adj value at each edge
__device__ int   g_ncnt  [NB*NN];      // neighbor count per row

__device__ __forceinline__ float leaky(float v) { return v >= 0.f ? v : NEG_SLOPE * v; }

// ---------------------------------------------------------------------------
// k12: per (b,j) block, 96 threads. Fused former k1+k2.
// Emits: dis row, deg, sd, aggx, nbr lists, A row, E row, sdikT row.
// Key algebra: sumC_j = (adj_j @ x) @ Wc = aggx_j @ Wc  (linear => no gather).
// sdikT recomputes dis(k,i) on the fly from x in shared (no cross-block dep).
// ---------------------------------------------------------------------------
__global__ void k12(const float* __restrict__ x, const float* __restrict__ adj,
                    const float* __restrict__ W1, const float* __restrict__ b1) {
    const int j = blockIdx.x, b = blockIdx.y;
    const int tid = threadIdx.x;                 // 0..95
    const int bj = b * NN + j;

    __shared__ float sx[NN * 17];                // padded x[b], conflict-free
    __shared__ float sadjv[NN];
    __shared__ float saggx[ND];
    __shared__ float red[6];
    __shared__ int   wc[3];
    __shared__ int   snb[NN];
    __shared__ float snv[NN];

    // bulk load x[b] (coalesced) + adj row j
    const float* xb = x + b * NN * ND;
    #pragma unroll
    for (int t = 0; t < ND; t++) {
        int idx = tid + t * NN;
        sx[(idx >> 4) * 17 + (idx & 15)] = xb[idx];
    }
    float av = adj[bj * NN + tid];
    sadjv[tid] = av;
    __syncthreads();

    // dis[j, tid]
    float acc = 1e-10f;
    #pragma unroll
    for (int d = 0; d < ND; d++) {
        float df = sx[j * 17 + d] - sx[tid * 17 + d];
        acc += df * df;
    }
    float dv = sqrtf(acc);
    g_dis[bj * NN + tid] = dv;

    // deg/sd reduction + ballot compaction setup
    {
        float va = av, vd = av * dv;
        #pragma unroll
        for (int off = 16; off; off >>= 1) {
            va += __shfl_xor_sync(0xffffffffu, va, off);
            vd += __shfl_xor_sync(0xffffffffu, vd, off);
        }
        int w = tid >> 5;
        if ((tid & 31) == 0) { red[w] = va; red[3 + w] = vd; }
    }
    unsigned m = __ballot_sync(0xffffffffu, av != 0.f);
    {
        int w = tid >> 5;
        if ((tid & 31) == 0) wc[w] = __popc(m);
    }
    __syncthreads();

    const float degv = red[0] + red[1] + red[2];
    const float sdv  = red[3] + red[4] + red[5];
    {
        int w = tid >> 5, lane = tid & 31;
        int base = (w > 0 ? wc[0] : 0) + (w > 1 ? wc[1] : 0);
        if (av != 0.f) {
            int pos = base + __popc(m & ((1u << lane) - 1u));
            snb[pos] = tid; snv[pos] = av;
        }
    }
    if (tid == 0) {
        g_deg[bj] = degv; g_sd[bj] = sdv;
        g_ncnt[bj] = wc[0] + wc[1] + wc[2];
    }
    __syncthreads();
    const int n = wc[0] + wc[1] + wc[2];

    // export compacted list; aggx (16 threads, ~n iterations of shared FMA)
    if (tid < n) { g_nbr[bj * NN + tid] = snb[tid]; g_nbrval[bj * NN + tid] = snv[tid]; }
    if (tid < ND) {
        float s = 0.f;
        for (int e = 0; e < n; e++) s += snv[e] * sx[snb[e] * 17 + tid];
        saggx[tid] = s;
        g_aggx[bj * ND + tid] = s;
    }
    __syncthreads();

    // sdikT row: thread = i; dis(k,i) recomputed from shared x
    {
        float sik = 0.f;
        #pragma unroll 2
        for (int e = 0; e < n; e++) {
            int k = snb[e];
            float d2 = 1e-10f;
            #pragma unroll
            for (int d = 0; d < ND; d++) {
                float df = sx[k * 17 + d] - sx[tid * 17 + d];
                d2 += df * df;
            }
            sik += snv[e] * sqrtf(d2);
        }
        g_sdikT[bj * NN + tid] = sik;
    }

    // A / E rows (thread = h). E folds Bm, bias, w_jk and sumC (=aggx@Wc).
    if (tid < H0) {
        float a0 = 0.f, bm = 0.f, cg = 0.f;
        #pragma unroll
        for (int d = 0; d < ND; d++) {
            float xv = sx[j * 17 + d];
            a0 += xv * W1[d * H0 + tid];
            bm += xv * W1[(ND + d) * H0 + tid];
            cg += saggx[d] * W1[(2 * ND + d) * H0 + tid];
        }
        g_A[bj * H0 + tid] = a0;
        g_E[bj * H0 + tid] = degv * (b1[tid] + bm) + sdv * W1[49 * H0 + tid] + cg;
    }
}

// ---------------------------------------------------------------------------
// k3: per (b,i) block, 96 threads.
// Per-edge scalars fetched in parallel (thread = edge); E rows staged to
// shared in chunks; hot loop is pure shared-memory FMA, one matvec per node.
// ---------------------------------------------------------------------------
__global__ void k3(const float* __restrict__ x, const float* __restrict__ W1,
                   const float* __restrict__ W2, const float* __restrict__ b2,
                   const float* __restrict__ W3, const float* __restrict__ b3,
                   float* __restrict__ out) {
    const int i = blockIdx.x, b = blockIdx.y;
    const int tid = threadIdx.x;                 // 0..95
    const int bi = b * NN + i;

    __shared__ float sWm[H0 * H1];               // W2 m3-block, 10 KB
    __shared__ float sE[ECH * 52];               // staged E chunk, 10 KB
    __shared__ int   snbr[NN];
    __shared__ float sval[NN], sP[NN], sQ[NN], sR[NN];
    __shared__ float sxi[ND], sax[ND];
    __shared__ float stsum[H0], sm2[H1];

    for (int p = tid; p < H0 * H1; p += NN)
        sWm[p] = W2[33 * H1 + p];

    const int n = g_ncnt[bi];                    // uniform broadcast load
    if (tid < n) {
        int jn = g_nbr[bi * NN + tid];
        float a = g_nbrval[bi * NN + tid];
        snbr[tid] = jn; sval[tid] = a;
        int bjn = b * NN + jn;
        float dj = g_deg[bjn];
        sP[tid] = dj;
        sQ[tid] = dj * g_dis[bi * NN + jn];
        sR[tid] = g_sdikT[bjn * NN + i];
    }
    if (tid < ND) { sxi[tid] = x[bi * ND + tid]; sax[tid] = g_aggx[bi * ND + tid]; }
    float rA = 0.f, rwij = 0.f, rwik = 0.f, rb2 = 0.f;
    if (tid < H0) {
        rA   = g_A[bi * H0 + tid];
        rwij = W1[48 * H0 + tid];
        rwik = W1[50 * H0 + tid];
        rb2  = b2[tid];
    }
    const float rdegi = g_deg[bi];
    const float rsdi  = g_sd[bi];
    __syncthreads();

    // chunked edge loop (uniform control flow)
    float tsum = 0.f;
    for (int c0 = 0; c0 < n; c0 += ECH) {
        const int ce = (n - c0) < ECH ? (n - c0) : ECH;
        for (int p = tid; p < ce * H0; p += NN) {
            int e = p / H0, h = p - e * H0;
            sE[e * 52 + h] = g_E[(b * NN + snbr[c0 + e]) * H0 + h];
        }
        __syncthreads();
        if (tid < H0) {
            #pragma unroll 4
            for (int e = 0; e < ce; e++) {
                float S = fmaf(sP[c0 + e], rA,
                          fmaf(sQ[c0 + e], rwij,
                          fmaf(sR[c0 + e], rwik, sE[e * 52 + tid])));
                float a = sval[c0 + e];
                tsum += a * leaky(a * S);
            }
        }
        __syncthreads();
    }
    if (tid < H0) stsum[tid] = tsum;
    __syncthreads();

    // m2_sum: one 50x50 matvec + factored linear terms
    if (tid < H1) {
        float acc = 0.f;
        #pragma unroll
        for (int h = 0; h < H0; h++) acc += stsum[h] * sWm[h * H1 + tid];
        float s1 = 0.f, s2 = 0.f;
        #pragma unroll
        for (int d = 0; d < ND; d++) {
            s1 += sxi[d] * W2[d * H1 + tid];
            s2 += sax[d] * W2[(ND + d) * H1 + tid];
        }
        acc += rdegi * (s1 + rb2) + s2 + rsdi * W2[2 * ND * H1 + tid];
        sm2[tid] = leaky(acc);
    }
    __syncthreads();

    // output GEMV (thread = output channel)
    if (tid < NOUT) {
        float s = b3[tid];
        #pragma unroll
        for (int d = 0; d < ND; d++) s += sxi[d] * W3[d * NOUT + tid];
        #pragma unroll 10
        for (int h = 0; h < H1; h++) s += sm2[h] * W3[(ND + h) * NOUT + tid];
        out[bi * NOUT + tid] = leaky(s);
    }
}

extern "C" void kernel_launch(void* const* d_in, const int* in_sizes, int n_in,
                              void* d_out, int out_size) {
    const float* x   = (const float*)d_in[0];
    const float* adj = (const float*)d_in[1];
    const float* W1  = (const float*)d_in[2];
    const float* b1  = (const float*)d_in[3];
    const float* W2  = (const float*)d_in[4];
    const float* b2  = (const float*)d_in[5];
    const float* W3  = (const float*)d_in[6];
    const float* b3  = (const float*)d_in[7];
    float* out = (float*)d_out;

    dim3 grid(NN, NB);
    k12<<<grid, NN>>>(x, adj, W1, b1);
    k3 <<<grid, NN>>>(x, W1, W2, b2, W3, b3, out);
}